// round 2
// baseline (speedup 1.0000x reference)
#include <cuda_runtime.h>
#include <cstdint>

#define B_ 2
#define S_ 2048
#define D_ 1024
#define H_ 16
#define U_ 64
#define QSCALE 0.125f   /* 1/sqrt(64) */

// scratch for attention output (16 MB) — static __device__, no allocation
__device__ float g_att[(size_t)B_ * S_ * D_];

// ---------------------------------------------------------------------------
// fast exp: degree-5 Taylor for 2^f on [-0.5,0.5] + exponent bit-add.
// Avoids MUFU (rt=8/SMSP would serialize 134M softmax exps into ~1ms).
// rel err ~2e-6, valid for x <= 0 (clamped at -80 -> exp ~ 1.8e-35, no denorm).
// ---------------------------------------------------------------------------
__device__ __forceinline__ float fast_exp(float x) {
    x = fmaxf(x, -80.0f);
    const float L2E = 1.4426950408889634f;
    float t  = fmaf(x, L2E, 12582912.0f);     // round-to-nearest int in low bits
    int   n  = __float_as_int(t);             // (0x4B400000 + nint); low 9 bits of base = 0
    float yr = t - 12582912.0f;               // rounded integer as float
    float f  = fmaf(x, L2E, -yr);             // frac in [-0.5, 0.5]
    float p  =        1.3333558146e-3f;
    p = fmaf(p, f,    9.6181291076e-3f);
    p = fmaf(p, f,    5.5504108664e-2f);
    p = fmaf(p, f,    2.4022650696e-1f);
    p = fmaf(p, f,    6.9314718056e-1f);
    p = fmaf(p, f,    1.0f);
    return __int_as_float(__float_as_int(p) + (n << 23));  // p * 2^nint
}

// ---------------------------------------------------------------------------
// Fused attention: per CTA = one (b, h, 64-query tile).
// Flash-style online softmax over 32 key tiles of 64.
// 256 threads as 16x16, each owns a 4x4 micro-tile.
// Shared (dynamic, ~70KB): Qs,Ks,Vs,Ps each 64x68 fp32 (+4 pad keeps float4
// alignment AND shifts banks between rows), kb[64] key-bias.
// ---------------------------------------------------------------------------
__global__ void __launch_bounds__(256) attn_kernel(
        const float* __restrict__ q,
        const float* __restrict__ k,
        const float* __restrict__ v,
        const float* __restrict__ mask) {
    extern __shared__ float sm[];
    float* Qs = sm;                 // 64*68
    float* Ks = Qs + 64 * 68;
    float* Vs = Ks + 64 * 68;
    float* Ps = Vs + 64 * 68;
    float* kb = Ps + 64 * 68;       // 64

    const int b  = blockIdx.z;
    const int h  = blockIdx.y;
    const int i0 = blockIdx.x * 64;
    const int tid = threadIdx.x;
    const int ty = tid >> 4;        // 0..15 : query-row group (rows 4*ty..4*ty+3)
    const int tx = tid & 15;        // 0..15 : col group

    const size_t bh_off = (size_t)b * S_ * D_ + (size_t)h * U_;

    // ---- load Q tile (pre-scaled by 1/sqrt(U)) ----
    {
        const int r  = tid >> 4;          // 16 rows/pass, 4 passes
        const int c  = (tid & 15) * 4;
        #pragma unroll
        for (int p = 0; p < 4; p++) {
            int row = r + p * 16;
            float4 t4 = *(const float4*)(q + bh_off + (size_t)(i0 + row) * D_ + c);
            t4.x *= QSCALE; t4.y *= QSCALE; t4.z *= QSCALE; t4.w *= QSCALE;
            *(float4*)(Qs + row * 68 + c) = t4;
        }
    }

    float acc[4][4] = {};
    float mrow[4] = {-1e30f, -1e30f, -1e30f, -1e30f};
    float lrow[4] = {};

    for (int jt = 0; jt < S_ / 64; jt++) {
        const int j0 = jt * 64;
        __syncthreads();   // prev PV done (iter 0: Q stores done)

        // ---- load K, V tiles + key bias ----
        {
            const int r = tid >> 4;
            const int c = (tid & 15) * 4;
            #pragma unroll
            for (int p = 0; p < 4; p++) {
                int row = r + p * 16;
                *(float4*)(Ks + row * 68 + c) =
                    *(const float4*)(k + bh_off + (size_t)(j0 + row) * D_ + c);
                *(float4*)(Vs + row * 68 + c) =
                    *(const float4*)(v + bh_off + (size_t)(j0 + row) * D_ + c);
            }
            if (tid < 64)
                kb[tid] = (1.0f - mask[(size_t)b * S_ + j0 + tid]) * 10000.0f;
        }
        __syncthreads();

        // ---- S = Q K^T  (4x4 micro-tile, float4 over u) ----
        float s[4][4] = {};
        #pragma unroll
        for (int u4 = 0; u4 < 16; u4++) {
            float4 q4[4], k4[4];
            #pragma unroll
            for (int i = 0; i < 4; i++)
                q4[i] = *(float4*)(Qs + (4 * ty + i) * 68 + 4 * u4);
            #pragma unroll
            for (int j = 0; j < 4; j++)
                k4[j] = *(float4*)(Ks + (4 * tx + j) * 68 + 4 * u4);
            #pragma unroll
            for (int i = 0; i < 4; i++)
                #pragma unroll
                for (int j = 0; j < 4; j++) {
                    s[i][j] = fmaf(q4[i].x, k4[j].x, s[i][j]);
                    s[i][j] = fmaf(q4[i].y, k4[j].y, s[i][j]);
                    s[i][j] = fmaf(q4[i].z, k4[j].z, s[i][j]);
                    s[i][j] = fmaf(q4[i].w, k4[j].w, s[i][j]);
                }
        }

        // ---- online softmax (row reductions across the 16-lane tx group) ----
        float kbv[4];
        #pragma unroll
        for (int j = 0; j < 4; j++) kbv[j] = kb[4 * tx + j];

        #pragma unroll
        for (int i = 0; i < 4; i++) {
            #pragma unroll
            for (int j = 0; j < 4; j++) s[i][j] -= kbv[j];
            float rm = fmaxf(fmaxf(s[i][0], s[i][1]), fmaxf(s[i][2], s[i][3]));
            #pragma unroll
            for (int o = 8; o > 0; o >>= 1)
                rm = fmaxf(rm, __shfl_xor_sync(0xffffffffu, rm, o));
            const float mnew  = fmaxf(mrow[i], rm);
            const float alpha = fast_exp(mrow[i] - mnew);
            float rs = 0.0f;
            #pragma unroll
            for (int j = 0; j < 4; j++) {
                float pv = fast_exp(s[i][j] - mnew);
                s[i][j] = pv;
                rs += pv;
            }
            #pragma unroll
            for (int o = 8; o > 0; o >>= 1)
                rs += __shfl_xor_sync(0xffffffffu, rs, o);
            lrow[i] = lrow[i] * alpha + rs;
            mrow[i] = mnew;
            #pragma unroll
            for (int j = 0; j < 4; j++) acc[i][j] *= alpha;
        }

        // ---- stage P ----
        #pragma unroll
        for (int i = 0; i < 4; i++)
            *(float4*)(Ps + (4 * ty + i) * 68 + 4 * tx) =
                make_float4(s[i][0], s[i][1], s[i][2], s[i][3]);
        __syncthreads();

        // ---- O += P V  (float4 over key dim) ----
        #pragma unroll
        for (int k4i = 0; k4i < 16; k4i++) {
            float4 p4[4], v4[4];
            #pragma unroll
            for (int i = 0; i < 4; i++)
                p4[i] = *(float4*)(Ps + (4 * ty + i) * 68 + 4 * k4i);
            #pragma unroll
            for (int t = 0; t < 4; t++)
                v4[t] = *(float4*)(Vs + (4 * k4i + t) * 68 + 4 * tx);
            #pragma unroll
            for (int i = 0; i < 4; i++) {
                acc[i][0] = fmaf(p4[i].x, v4[0].x, acc[i][0]);
                acc[i][1] = fmaf(p4[i].x, v4[0].y, acc[i][1]);
                acc[i][2] = fmaf(p4[i].x, v4[0].z, acc[i][2]);
                acc[i][3] = fmaf(p4[i].x, v4[0].w, acc[i][3]);
                acc[i][0] = fmaf(p4[i].y, v4[1].x, acc[i][0]);
                acc[i][1] = fmaf(p4[i].y, v4[1].y, acc[i][1]);
                acc[i][2] = fmaf(p4[i].y, v4[1].z, acc[i][2]);
                acc[i][3] = fmaf(p4[i].y, v4[1].w, acc[i][3]);
                acc[i][0] = fmaf(p4[i].z, v4[2].x, acc[i][0]);
                acc[i][1] = fmaf(p4[i].z, v4[2].y, acc[i][1]);
                acc[i][2] = fmaf(p4[i].z, v4[2].z, acc[i][2]);
                acc[i][3] = fmaf(p4[i].z, v4[2].w, acc[i][3]);
                acc[i][0] = fmaf(p4[i].w, v4[3].x, acc[i][0]);
                acc[i][1] = fmaf(p4[i].w, v4[3].y, acc[i][1]);
                acc[i][2] = fmaf(p4[i].w, v4[3].z, acc[i][2]);
                acc[i][3] = fmaf(p4[i].w, v4[3].w, acc[i][3]);
            }
        }
    }

    // ---- normalize and write attended ----
    #pragma unroll
    for (int i = 0; i < 4; i++) {
        const float inv = 1.0f / lrow[i];
        float4 o4 = make_float4(acc[i][0] * inv, acc[i][1] * inv,
                                acc[i][2] * inv, acc[i][3] * inv);
        *(float4*)(g_att + ((size_t)b * S_ + i0 + 4 * ty + i) * D_
                          + (size_t)h * U_ + 4 * tx) = o4;
    }
}

// ---------------------------------------------------------------------------
// Output projection: out[M=4096, N=1024] = g_att @ W_o[1024,1024]
// 64x64 tile, KT=32, 256 threads, 4x4 micro-tile. A staged transposed
// (As[k][m]) so the inner loop is 2x LDS.128 per 16 FMA.
// ---------------------------------------------------------------------------
__global__ void __launch_bounds__(256) proj_kernel(
        const float* __restrict__ W, float* __restrict__ out) {
    __shared__ float As[32][68];    // [k][m]
    __shared__ float Bs[32][68];    // [k][n]

    const int n0 = blockIdx.x * 64;
    const int m0 = blockIdx.y * 64;
    const int tid = threadIdx.x;
    const int ty = tid >> 4;
    const int tx = tid & 15;

    const float* A = g_att;
    float acc[4][4] = {};

    for (int k0 = 0; k0 < D_; k0 += 32) {
        __syncthreads();
        // A tile 64x32, stored transposed
        {
            const int m  = tid >> 3;           // 0..31
            const int kk = (tid & 7) * 4;      // 0..28
            #pragma unroll
            for (int p = 0; p < 2; p++) {
                int mm = m + p * 32;
                float4 a4 = *(const float4*)(A + (size_t)(m0 + mm) * D_ + k0 + kk);
                As[kk + 0][mm] = a4.x;
                As[kk + 1][mm] = a4.y;
                As[kk + 2][mm] = a4.z;
                As[kk + 3][mm] = a4.w;
            }
        }
        // B tile 32x64, natural layout
        {
            const int kr = tid >> 4;           // 0..15
            const int n  = (tid & 15) * 4;
            #pragma unroll
            for (int p = 0; p < 2; p++) {
                *(float4*)(&Bs[kr + p * 16][n]) =
                    *(const float4*)(W + (size_t)(k0 + kr + p * 16) * D_ + n0 + n);
            }
        }
        __syncthreads();

        #pragma unroll
        for (int kk = 0; kk < 32; kk++) {
            float4 a4 = *(float4*)&As[kk][4 * ty];
            float4 b4 = *(float4*)&Bs[kk][4 * tx];
            acc[0][0] = fmaf(a4.x, b4.x, acc[0][0]);
            acc[0][1] = fmaf(a4.x, b4.y, acc[0][1]);
            acc[0][2] = fmaf(a4.x, b4.z, acc[0][2]);
            acc[0][3] = fmaf(a4.x, b4.w, acc[0][3]);
            acc[1][0] = fmaf(a4.y, b4.x, acc[1][0]);
            acc[1][1] = fmaf(a4.y, b4.y, acc[1][1]);
            acc[1][2] = fmaf(a4.y, b4.z, acc[1][2]);
            acc[1][3] = fmaf(a4.y, b4.w, acc[1][3]);
            acc[2][0] = fmaf(a4.z, b4.x, acc[2][0]);
            acc[2][1] = fmaf(a4.z, b4.y, acc[2][1]);
            acc[2][2] = fmaf(a4.z, b4.z, acc[2][2]);
            acc[2][3] = fmaf(a4.z, b4.w, acc[2][3]);
            acc[3][0] = fmaf(a4.w, b4.x, acc[3][0]);
            acc[3][1] = fmaf(a4.w, b4.y, acc[3][1]);
            acc[3][2] = fmaf(a4.w, b4.z, acc[3][2]);
            acc[3][3] = fmaf(a4.w, b4.w, acc[3][3]);
        }
    }

    #pragma unroll
    for (int i = 0; i < 4; i++) {
        *(float4*)(out + (size_t)(m0 + 4 * ty + i) * D_ + n0 + 4 * tx) =
            make_float4(acc[i][0], acc[i][1], acc[i][2], acc[i][3]);
    }
}

extern "C" void kernel_launch(void* const* d_in, const int* in_sizes, int n_in,
                              void* d_out, int out_size) {
    const float* q    = (const float*)d_in[0];
    const float* k    = (const float*)d_in[1];
    const float* v    = (const float*)d_in[2];
    const float* mask = (const float*)d_in[3];
    const float* W    = (const float*)d_in[4];
    float* out = (float*)d_out;

    const int smem = (4 * 64 * 68 + 64) * (int)sizeof(float);   // 69,888 B
    cudaFuncSetAttribute(attn_kernel,
                         cudaFuncAttributeMaxDynamicSharedMemorySize, smem);

    dim3 g1(S_ / 64, H_, B_);           // (32, 16, 2) = 1024 CTAs
    attn_kernel<<<g1, 256, smem>>>(q, k, v, mask);

    dim3 g2(D_ / 64, (B_ * S_) / 64);   // (16, 64) = 1024 CTAs
    proj_kernel<<<g2, 256>>>(W, out);
}

// round 6
// speedup vs baseline: 3.8662x; 3.8662x over previous
#include <cuda_runtime.h>
#include <cuda_bf16.h>
#include <cstdint>

#define B_ 2
#define S_ 2048
#define D_ 1024
#define H_ 16
#define U_ 64
#define QSCALE 0.125f
#define NELEM ((size_t)B_ * S_ * D_)   /* 4,194,304 */
#define LDT 72                          /* attn smem tile stride in halves */

// ---------------- static device scratch (no allocation allowed) --------------
// POD unsigned short (bf16 bit pattern) — guaranteed zero static-init code.
typedef unsigned short bf16raw;
__device__ bf16raw g_qhi[NELEM], g_qlo[NELEM];
__device__ bf16raw g_khi[NELEM], g_klo[NELEM];
__device__ bf16raw g_vhi[NELEM], g_vlo[NELEM];
__device__ bf16raw g_whi[D_ * D_], g_wlo[D_ * D_];
__device__ bf16raw g_ahi[NELEM], g_alo[NELEM];

// ---------------- helpers ----------------------------------------------------
__device__ __forceinline__ uint32_t smaddr(const void* p) {
    return (uint32_t)__cvta_generic_to_shared(p);
}
__device__ __forceinline__ void ldsm_x4(uint32_t r[4], uint32_t a) {
    asm volatile("ldmatrix.sync.aligned.m8n8.x4.shared.b16 {%0,%1,%2,%3}, [%4];"
                 : "=r"(r[0]), "=r"(r[1]), "=r"(r[2]), "=r"(r[3]) : "r"(a));
}
__device__ __forceinline__ void ldsm_x4t(uint32_t r[4], uint32_t a) {
    asm volatile("ldmatrix.sync.aligned.m8n8.x4.trans.shared.b16 {%0,%1,%2,%3}, [%4];"
                 : "=r"(r[0]), "=r"(r[1]), "=r"(r[2]), "=r"(r[3]) : "r"(a));
}
__device__ __forceinline__ void mma_bf16(float d[4], const uint32_t a[4],
                                         uint32_t b0, uint32_t b1) {
    asm volatile("mma.sync.aligned.m16n8k16.row.col.f32.bf16.bf16.f32 "
                 "{%0,%1,%2,%3}, {%4,%5,%6,%7}, {%8,%9}, {%0,%1,%2,%3};"
                 : "+f"(d[0]), "+f"(d[1]), "+f"(d[2]), "+f"(d[3])
                 : "r"(a[0]), "r"(a[1]), "r"(a[2]), "r"(a[3]), "r"(b0), "r"(b1));
}
// split (x,y) into packed bf16 hi pair + bf16 residual pair
__device__ __forceinline__ void split2(float x, float y, uint32_t& hi, uint32_t& lo) {
    __nv_bfloat162 h = __floats2bfloat162_rn(x, y);
    hi = *reinterpret_cast<uint32_t*>(&h);
    __nv_bfloat162 l = __floats2bfloat162_rn(x - __bfloat162float(h.x),
                                             y - __bfloat162float(h.y));
    lo = *reinterpret_cast<uint32_t*>(&l);
}
// polynomial exp on FMA pipe (MUFU rt=8 would serialize 134M exps)
__device__ __forceinline__ float fast_exp(float x) {
    x = fmaxf(x, -80.0f);
    const float L2E = 1.4426950408889634f;
    float t  = fmaf(x, L2E, 12582912.0f);
    int   n  = __float_as_int(t);
    float yr = t - 12582912.0f;
    float f  = fmaf(x, L2E, -yr);
    float p  =        1.3333558146e-3f;
    p = fmaf(p, f,    9.6181291076e-3f);
    p = fmaf(p, f,    5.5504108664e-2f);
    p = fmaf(p, f,    2.4022650696e-1f);
    p = fmaf(p, f,    6.9314718056e-1f);
    p = fmaf(p, f,    1.0f);
    return __int_as_float(__float_as_int(p) + (n << 23));
}

// ---------------- fp32 -> bf16 hi/lo pre-convert -----------------------------
__global__ void cvt_split(const float* __restrict__ src, int which,
                          float scale, int n4) {
    int i = blockIdx.x * blockDim.x + threadIdx.x;
    if (i >= n4) return;
    bf16raw *hi, *lo;
    switch (which) {
        case 0: hi = g_qhi; lo = g_qlo; break;
        case 1: hi = g_khi; lo = g_klo; break;
        case 2: hi = g_vhi; lo = g_vlo; break;
        default: hi = g_whi; lo = g_wlo; break;
    }
    float4 x = reinterpret_cast<const float4*>(src)[i];
    x.x *= scale; x.y *= scale; x.z *= scale; x.w *= scale;
    uint32_t h0, l0, h1, l1;
    split2(x.x, x.y, h0, l0);
    split2(x.z, x.w, h1, l1);
    reinterpret_cast<uint32_t*>(hi)[2 * i]     = h0;
    reinterpret_cast<uint32_t*>(hi)[2 * i + 1] = h1;
    reinterpret_cast<uint32_t*>(lo)[2 * i]     = l0;
    reinterpret_cast<uint32_t*>(lo)[2 * i + 1] = l1;
}

// ---------------- fused attention (tensor cores, hi/lo split) ----------------
// CTA = (b, h, 64 queries). 4 warps x 16 rows. Key loop in tiles of 64.
__global__ void __launch_bounds__(128) attn_mma_kernel(const float* __restrict__ mask) {
    extern __shared__ bf16raw smh[];
    bf16raw* Qh = smh;
    bf16raw* Ql = Qh + 64 * LDT;
    bf16raw* Kh = Ql + 64 * LDT;
    bf16raw* Kl = Kh + 64 * LDT;
    bf16raw* Vh = Kl + 64 * LDT;
    bf16raw* Vl = Vh + 64 * LDT;
    float* kb = reinterpret_cast<float*>(Vl + 64 * LDT);

    const int b = blockIdx.z, h = blockIdx.y;
    const int i0 = blockIdx.x * 64;
    const int tid = threadIdx.x;
    const int warp = tid >> 5, lane = tid & 31;
    const size_t bh = (size_t)b * S_ * D_ + (size_t)h * U_;

    // stage Q tiles
    #pragma unroll
    for (int p = 0; p < 4; p++) {
        int idx = tid + p * 128;
        int r = idx >> 3, c = (idx & 7) * 8;
        size_t g = bh + (size_t)(i0 + r) * D_ + c;
        *reinterpret_cast<uint4*>(Qh + r * LDT + c) = *reinterpret_cast<const uint4*>(g_qhi + g);
        *reinterpret_cast<uint4*>(Ql + r * LDT + c) = *reinterpret_cast<const uint4*>(g_qlo + g);
    }
    __syncthreads();

    // Q fragments resident in registers for the whole kernel
    uint32_t qh[4][4], ql[4][4];
    const int m0 = warp * 16;
    {
        int ar = m0 + (lane & 15);
        int ac = (lane >> 4) * 8;
        #pragma unroll
        for (int kc = 0; kc < 4; kc++) {
            ldsm_x4(qh[kc], smaddr(Qh + ar * LDT + kc * 16 + ac));
            ldsm_x4(ql[kc], smaddr(Ql + ar * LDT + kc * 16 + ac));
        }
    }

    float oacc[8][4];
    #pragma unroll
    for (int g = 0; g < 8; g++) { oacc[g][0] = oacc[g][1] = oacc[g][2] = oacc[g][3] = 0.f; }
    float mr0 = -1e30f, mr1 = -1e30f, lr0 = 0.f, lr1 = 0.f;

    const int krow = (lane & 7) + ((lane >> 4) << 3);
    const int kcol = ((lane >> 3) & 1) * 8;
    const int vrow = lane & 15;
    const int vcol = (lane >> 4) * 8;
    const int cq = 2 * (lane & 3);

    for (int jt = 0; jt < S_ / 64; jt++) {
        const int j0 = jt * 64;
        __syncthreads();
        #pragma unroll
        for (int p = 0; p < 4; p++) {
            int idx = tid + p * 128;
            int r = idx >> 3, c = (idx & 7) * 8;
            size_t g = bh + (size_t)(j0 + r) * D_ + c;
            *reinterpret_cast<uint4*>(Kh + r * LDT + c) = *reinterpret_cast<const uint4*>(g_khi + g);
            *reinterpret_cast<uint4*>(Kl + r * LDT + c) = *reinterpret_cast<const uint4*>(g_klo + g);
            *reinterpret_cast<uint4*>(Vh + r * LDT + c) = *reinterpret_cast<const uint4*>(g_vhi + g);
            *reinterpret_cast<uint4*>(Vl + r * LDT + c) = *reinterpret_cast<const uint4*>(g_vlo + g);
        }
        if (tid < 64) kb[tid] = (1.0f - mask[(size_t)b * S_ + j0 + tid]) * 10000.0f;
        __syncthreads();

        // ---- S = Q K^T : hi*hi + hi*lo + lo*hi -----------------------------
        float sacc[8][4];
        #pragma unroll
        for (int t = 0; t < 8; t++) { sacc[t][0] = sacc[t][1] = sacc[t][2] = sacc[t][3] = 0.f; }

        #pragma unroll
        for (int kc = 0; kc < 4; kc++) {
            #pragma unroll
            for (int g = 0; g < 4; g++) {
                uint32_t bh4[4], bl4[4];
                int ro = (g * 16 + krow) * LDT + kc * 16 + kcol;
                ldsm_x4(bh4, smaddr(Kh + ro));
                ldsm_x4(bl4, smaddr(Kl + ro));
                mma_bf16(sacc[2 * g],     qh[kc], bh4[0], bh4[1]);
                mma_bf16(sacc[2 * g + 1], qh[kc], bh4[2], bh4[3]);
                mma_bf16(sacc[2 * g],     qh[kc], bl4[0], bl4[1]);
                mma_bf16(sacc[2 * g + 1], qh[kc], bl4[2], bl4[3]);
                mma_bf16(sacc[2 * g],     ql[kc], bh4[0], bh4[1]);
                mma_bf16(sacc[2 * g + 1], ql[kc], bh4[2], bh4[3]);
            }
        }

        // ---- bias + online softmax (on m16n8 accumulator layout) -----------
        #pragma unroll
        for (int t = 0; t < 8; t++) {
            float2 kv = *reinterpret_cast<float2*>(kb + 8 * t + cq);
            sacc[t][0] -= kv.x; sacc[t][1] -= kv.y;
            sacc[t][2] -= kv.x; sacc[t][3] -= kv.y;
        }
        float rm0 = -1e30f, rm1 = -1e30f;
        #pragma unroll
        for (int t = 0; t < 8; t++) {
            rm0 = fmaxf(rm0, fmaxf(sacc[t][0], sacc[t][1]));
            rm1 = fmaxf(rm1, fmaxf(sacc[t][2], sacc[t][3]));
        }
        rm0 = fmaxf(rm0, __shfl_xor_sync(0xffffffffu, rm0, 1));
        rm0 = fmaxf(rm0, __shfl_xor_sync(0xffffffffu, rm0, 2));
        rm1 = fmaxf(rm1, __shfl_xor_sync(0xffffffffu, rm1, 1));
        rm1 = fmaxf(rm1, __shfl_xor_sync(0xffffffffu, rm1, 2));
        const float mn0 = fmaxf(mr0, rm0), mn1 = fmaxf(mr1, rm1);
        const float a0 = fast_exp(mr0 - mn0), a1 = fast_exp(mr1 - mn1);
        mr0 = mn0; mr1 = mn1;
        float rs0 = 0.f, rs1 = 0.f;
        #pragma unroll
        for (int t = 0; t < 8; t++) {
            sacc[t][0] = fast_exp(sacc[t][0] - mn0);
            sacc[t][1] = fast_exp(sacc[t][1] - mn0);
            sacc[t][2] = fast_exp(sacc[t][2] - mn1);
            sacc[t][3] = fast_exp(sacc[t][3] - mn1);
            rs0 += sacc[t][0] + sacc[t][1];
            rs1 += sacc[t][2] + sacc[t][3];
        }
        rs0 += __shfl_xor_sync(0xffffffffu, rs0, 1);
        rs0 += __shfl_xor_sync(0xffffffffu, rs0, 2);
        rs1 += __shfl_xor_sync(0xffffffffu, rs1, 1);
        rs1 += __shfl_xor_sync(0xffffffffu, rs1, 2);
        lr0 = lr0 * a0 + rs0;
        lr1 = lr1 * a1 + rs1;
        #pragma unroll
        for (int g = 0; g < 8; g++) {
            oacc[g][0] *= a0; oacc[g][1] *= a0;
            oacc[g][2] *= a1; oacc[g][3] *= a1;
        }

        // ---- O += P V : P split in registers, V hi/lo from smem ------------
        #pragma unroll
        for (int kc = 0; kc < 4; kc++) {
            uint32_t ph[4], pl[4];
            const float* s0 = sacc[2 * kc];
            const float* s1 = sacc[2 * kc + 1];
            split2(s0[0], s0[1], ph[0], pl[0]);
            split2(s0[2], s0[3], ph[1], pl[1]);
            split2(s1[0], s1[1], ph[2], pl[2]);
            split2(s1[2], s1[3], ph[3], pl[3]);
            #pragma unroll
            for (int g = 0; g < 4; g++) {
                uint32_t bh4[4], bl4[4];
                int ro = (kc * 16 + vrow) * LDT + g * 16 + vcol;
                ldsm_x4t(bh4, smaddr(Vh + ro));
                ldsm_x4t(bl4, smaddr(Vl + ro));
                mma_bf16(oacc[2 * g],     ph, bh4[0], bh4[1]);
                mma_bf16(oacc[2 * g + 1], ph, bh4[2], bh4[3]);
                mma_bf16(oacc[2 * g],     ph, bl4[0], bl4[1]);
                mma_bf16(oacc[2 * g + 1], ph, bl4[2], bl4[3]);
                mma_bf16(oacc[2 * g],     pl, bh4[0], bh4[1]);
                mma_bf16(oacc[2 * g + 1], pl, bh4[2], bh4[3]);
            }
        }
    }

    // ---- epilogue: normalize, split to bf16 hi/lo for projection -----------
    // NOTE: global row includes the batch offset b*S_ (this was the R4 bug).
    const float inv0 = 1.0f / lr0, inv1 = 1.0f / lr1;
    const int r0 = b * S_ + i0 + m0 + (lane >> 2);
    #pragma unroll
    for (int g = 0; g < 8; g++) {
        int c = h * U_ + g * 8 + cq;
        uint32_t hh, ll;
        split2(oacc[g][0] * inv0, oacc[g][1] * inv0, hh, ll);
        *reinterpret_cast<uint32_t*>(g_ahi + (size_t)r0 * D_ + c) = hh;
        *reinterpret_cast<uint32_t*>(g_alo + (size_t)r0 * D_ + c) = ll;
        split2(oacc[g][2] * inv1, oacc[g][3] * inv1, hh, ll);
        *reinterpret_cast<uint32_t*>(g_ahi + (size_t)(r0 + 8) * D_ + c) = hh;
        *reinterpret_cast<uint32_t*>(g_alo + (size_t)(r0 + 8) * D_ + c) = ll;
    }
}

// ---------------- projection: out = att @ W (tensor cores, hi/lo split) ------
__global__ void __launch_bounds__(256) proj_mma_kernel(float* __restrict__ out) {
    __shared__ bf16raw Ah[128][40], Al[128][40];
    __shared__ bf16raw Wh[32][136], Wl[32][136];
    const int n0 = blockIdx.x * 128, m0 = blockIdx.y * 128;
    const int tid = threadIdx.x, warp = tid >> 5, lane = tid & 31;
    const int wm = (warp >> 2) * 64;
    const int wn = (warp & 3) * 32;

    float acc[4][4][4];
    #pragma unroll
    for (int i = 0; i < 4; i++)
        #pragma unroll
        for (int j = 0; j < 4; j++)
            acc[i][j][0] = acc[i][j][1] = acc[i][j][2] = acc[i][j][3] = 0.f;

    const int ar = lane & 15, ac = (lane >> 4) * 8;

    for (int k0 = 0; k0 < D_; k0 += 32) {
        __syncthreads();
        #pragma unroll
        for (int p = 0; p < 2; p++) {
            int idx = tid + p * 256;
            int r = idx >> 2, c = (idx & 3) * 8;
            size_t g = (size_t)(m0 + r) * D_ + k0 + c;
            *reinterpret_cast<uint4*>(&Ah[r][c]) = *reinterpret_cast<const uint4*>(g_ahi + g);
            *reinterpret_cast<uint4*>(&Al[r][c]) = *reinterpret_cast<const uint4*>(g_alo + g);
        }
        #pragma unroll
        for (int p = 0; p < 2; p++) {
            int idx = tid + p * 256;
            int r = idx >> 4, c = (idx & 15) * 8;
            size_t g = (size_t)(k0 + r) * D_ + n0 + c;
            *reinterpret_cast<uint4*>(&Wh[r][c]) = *reinterpret_cast<const uint4*>(g_whi + g);
            *reinterpret_cast<uint4*>(&Wl[r][c]) = *reinterpret_cast<const uint4*>(g_wlo + g);
        }
        __syncthreads();

        #pragma unroll
        for (int kc = 0; kc < 2; kc++) {
            const int kk = kc * 16;
            uint32_t ah[4][4], al[4][4];
            #pragma unroll
            for (int mi = 0; mi < 4; mi++) {
                ldsm_x4(ah[mi], smaddr(&Ah[wm + mi * 16 + ar][kk + ac]));
                ldsm_x4(al[mi], smaddr(&Al[wm + mi * 16 + ar][kk + ac]));
            }
            #pragma unroll
            for (int gg = 0; gg < 2; gg++) {
                uint32_t bh4[4], bl4[4];
                ldsm_x4t(bh4, smaddr(&Wh[kk + ar][wn + gg * 16 + ac]));
                ldsm_x4t(bl4, smaddr(&Wl[kk + ar][wn + gg * 16 + ac]));
                #pragma unroll
                for (int mi = 0; mi < 4; mi++) {
                    mma_bf16(acc[mi][2 * gg],     ah[mi], bh4[0], bh4[1]);
                    mma_bf16(acc[mi][2 * gg + 1], ah[mi], bh4[2], bh4[3]);
                    mma_bf16(acc[mi][2 * gg],     ah[mi], bl4[0], bl4[1]);
                    mma_bf16(acc[mi][2 * gg + 1], ah[mi], bl4[2], bl4[3]);
                    mma_bf16(acc[mi][2 * gg],     al[mi], bh4[0], bh4[1]);
                    mma_bf16(acc[mi][2 * gg + 1], al[mi], bh4[2], bh4[3]);
                }
            }
        }
    }

    const int cq = 2 * (lane & 3);
    #pragma unroll
    for (int mi = 0; mi < 4; mi++) {
        int row = m0 + wm + mi * 16 + (lane >> 2);
        #pragma unroll
        for (int ni = 0; ni < 4; ni++) {
            int col = n0 + wn + ni * 8 + cq;
            *reinterpret_cast<float2*>(out + (size_t)row * D_ + col) =
                make_float2(acc[mi][ni][0], acc[mi][ni][1]);
            *reinterpret_cast<float2*>(out + (size_t)(row + 8) * D_ + col) =
                make_float2(acc[mi][ni][2], acc[mi][ni][3]);
        }
    }
}

// ---------------- launch ------------------------------------------------------
extern "C" void kernel_launch(void* const* d_in, const int* in_sizes, int n_in,
                              void* d_out, int out_size) {
    const float* q    = (const float*)d_in[0];
    const float* k    = (const float*)d_in[1];
    const float* v    = (const float*)d_in[2];
    const float* mask = (const float*)d_in[3];
    const float* W    = (const float*)d_in[4];
    float* out = (float*)d_out;

    const int n4 = (int)(NELEM / 4);            // 1,048,576
    cvt_split<<<n4 / 256, 256>>>(q, 0, QSCALE, n4);
    cvt_split<<<n4 / 256, 256>>>(k, 1, 1.0f, n4);
    cvt_split<<<n4 / 256, 256>>>(v, 2, 1.0f, n4);
    const int w4 = D_ * D_ / 4;                 // 262,144
    cvt_split<<<w4 / 256, 256>>>(W, 3, 1.0f, w4);

    const int smem = 6 * 64 * LDT * 2 + 64 * 4; // 55,552 B
    cudaFuncSetAttribute(attn_mma_kernel,
                         cudaFuncAttributeMaxDynamicSharedMemorySize, smem);
    attn_mma_kernel<<<dim3(S_ / 64, H_, B_), 128, smem>>>(mask);

    proj_mma_kernel<<<dim3(D_ / 128, (B_ * S_) / 128), 256>>>(out);
}